// round 10
// baseline (speedup 1.0000x reference)
#include <cuda_runtime.h>
#include <cuda_bf16.h>
#include <cstdint>

#define NNODES 100000
#define EDGES  1000000
#define INF 64
#define OUTF 64
#define NB 391                 // ceil(100000/256) scan tiles
#define GEMM_BLOCKS 1563       // ceil(100000/64)

typedef unsigned long long ull;

// Scratch (__device__ globals; runtime allocation forbidden).
__device__ int    g_cnt[NNODES];          // zero at entry; re-zeroed by scan_a tail
__device__ int    g_excl[NNODES];
__device__ int    g_rowptr[NNODES + 1];
__device__ int    g_cursor[NNODES];
__device__ int    g_adj[EDGES];
__device__ int    g_bsums[NB];
__device__ float4 g_msg4[(size_t)NNODES * (INF / 4)];   // meaned neighbor feats

// ---------------------------------------------------------------------------
// f32x2 packed-FMA helpers
// ---------------------------------------------------------------------------
__device__ __forceinline__ void fma2(ull& d, ull a, ull b) {
    asm("fma.rn.f32x2 %0, %1, %2, %0;" : "+l"(d) : "l"(a), "l"(b));
}
__device__ __forceinline__ ull dup2(float x) {
    ull r; asm("mov.b64 %0, {%1, %2};" : "=l"(r) : "f"(x), "f"(x)); return r;
}
__device__ __forceinline__ void unpack2(ull v, float& x, float& y) {
    asm("mov.b64 {%0, %1}, %2;" : "=f"(x), "=f"(y) : "l"(v));
}

// ---------------------------------------------------------------------------
// Half-GEMM: acc += srcmat[64n x 64k] @ W[:, wofs:wofs+64]^T for one tile.
// 256 threads, thread tile 4 nodes x 4 outs (f32x2 pairs). R9-proven.
// ---------------------------------------------------------------------------
__device__ __forceinline__ void half_gemm(const float* __restrict__ srcmat,
                                          const float* __restrict__ W,
                                          int wofs, int gn, int tid,
                                          float* As, float* Ws,
                                          ull acc[2][4]) {
    for (int i = tid; i < 64 * 64; i += 256) {
        int n = i >> 6, k = i & 63;
        int ng = gn + n;
        As[k * 68 + n] = (ng < NNODES) ? srcmat[(size_t)ng * INF + k] : 0.0f;
    }
    for (int i = tid; i < 64 * 64; i += 256) {
        int o = i >> 6, k = i & 63;
        Ws[k * 68 + o] = W[o * 128 + wofs + k];
    }
    __syncthreads();

    int n0 = (tid & 15) * 4;
    int o0 = (tid >> 4) * 4;
#pragma unroll 8
    for (int kk = 0; kk < 64; kk++) {
        ulonglong2 av = *(const ulonglong2*)&As[kk * 68 + n0];
        float4 wv = *(const float4*)&Ws[kk * 68 + o0];
        ull ap[2] = {av.x, av.y};
        ull wp[4] = {dup2(wv.x), dup2(wv.y), dup2(wv.z), dup2(wv.w)};
#pragma unroll
        for (int j = 0; j < 2; j++)
#pragma unroll
            for (int oi = 0; oi < 4; oi++)
                fma2(acc[j][oi], ap[j], wp[oi]);
    }
}

// ---------------------------------------------------------------------------
// K1: degree histogram (R8-proven, 1 edge/thread)
// ---------------------------------------------------------------------------
__global__ void hist_kernel(const int* __restrict__ dst, int E) {
    int e = blockIdx.x * blockDim.x + threadIdx.x;
    if (e < E) atomicAdd(&g_cnt[dst[e]], 1);
}

// ---------------------------------------------------------------------------
// K2: per-block inclusive scan -> block-local exclusive + block totals;
// tail re-zeroes g_cnt (own element; race-free).
// ---------------------------------------------------------------------------
__global__ void scan_a_kernel() {
    __shared__ int s[256];
    int tid = threadIdx.x;
    int i = blockIdx.x * 256 + tid;
    int c = (i < NNODES) ? g_cnt[i] : 0;
    s[tid] = c;
    __syncthreads();
#pragma unroll
    for (int off = 1; off < 256; off <<= 1) {
        int v = (tid >= off) ? s[tid - off] : 0;
        __syncthreads();
        s[tid] += v;
        __syncthreads();
    }
    if (i < NNODES) {
        g_excl[i] = s[tid] - c;
        g_cnt[i] = 0;
    }
    if (tid == 255) g_bsums[blockIdx.x] = s[255];
}

// ---------------------------------------------------------------------------
// K3: block bid: base = sum(g_bsums[0..bid-1]); write rowptr + cursor.
// ---------------------------------------------------------------------------
__global__ void scan_c_kernel(int E) {
    __shared__ int r[256];
    int tid = threadIdx.x, bid = blockIdx.x;
    int partial = 0;
    for (int j = tid; j < bid; j += 256) partial += g_bsums[j];
    r[tid] = partial;
    __syncthreads();
#pragma unroll
    for (int off = 128; off > 0; off >>= 1) {
        if (tid < off) r[tid] += r[tid + off];
        __syncthreads();
    }
    int base = r[0];

    int i = bid * 256 + tid;
    if (i < NNODES) {
        int ex = base + g_excl[i];
        g_rowptr[i] = ex;
        g_cursor[i] = ex;
    }
    if (i == 0) g_rowptr[NNODES] = E;
}

// ---------------------------------------------------------------------------
// K4: interleaved fill + partial-GEMM.  Role by bid%7: r<5 -> fill (latency-
// bound atomics, issue ~5%), r>=5 -> partial = h@W1 + b into out (compute-
// bound) — both roles resident in every wave so the GEMM runs in fill's idle
// issue slots.  fill body is the R7/R8-proven 1-edge/thread form.
// ---------------------------------------------------------------------------
__global__ __launch_bounds__(256)
void fill_partial_kernel(const int* __restrict__ src,
                         const int* __restrict__ dst, int E, int fill_blocks,
                         const float* __restrict__ h,
                         const float* __restrict__ W,
                         const float* __restrict__ b,
                         float* __restrict__ out) {
    __shared__ float As[64 * 68];
    __shared__ float Ws[64 * 68];
    int tid = threadIdx.x;
    int q = blockIdx.x / 7;
    int r = blockIdx.x % 7;

    if (r < 5) {
        int fb = q * 5 + r;
        if (fb >= fill_blocks) return;
        int e = fb * 256 + tid;
        if (e < E) {
            int pos = atomicAdd(&g_cursor[dst[e]], 1);
            g_adj[pos] = src[e];
        }
        return;
    }

    int gb = q * 2 + (r - 5);
    if (gb >= GEMM_BLOCKS) return;
    int gn = gb * 64;

    ull acc[2][4];
#pragma unroll
    for (int j = 0; j < 2; j++)
#pragma unroll
        for (int oi = 0; oi < 4; oi++) acc[j][oi] = 0ULL;

    half_gemm(h, W, 0, gn, tid, As, Ws, acc);

    int n0 = (tid & 15) * 4;
    int o0 = (tid >> 4) * 4;
    float4 bv = *(const float4*)&b[o0];
    float bb[4] = {bv.x, bv.y, bv.z, bv.w};
#pragma unroll
    for (int j = 0; j < 2; j++) {
        float x0[4], x1[4];
#pragma unroll
        for (int oi = 0; oi < 4; oi++) unpack2(acc[j][oi], x0[oi], x1[oi]);
        int n = gn + n0 + 2 * j;
        if (n < NNODES) {
            float4 rr; rr.x = x0[0] + bb[0]; rr.y = x0[1] + bb[1];
            rr.z = x0[2] + bb[2]; rr.w = x0[3] + bb[3];
            *(float4*)&out[(size_t)n * OUTF + o0] = rr;
        }
        if (n + 1 < NNODES) {
            float4 rr; rr.x = x1[0] + bb[0]; rr.y = x1[1] + bb[1];
            rr.z = x1[2] + bb[2]; rr.w = x1[3] + bb[3];
            *(float4*)&out[(size_t)(n + 1) * OUTF + o0] = rr;
        }
    }
}

// ---------------------------------------------------------------------------
// K5: gather-mean (R8-proven). 1 warp/node; half-warp x float4 rows.
// ---------------------------------------------------------------------------
__global__ __launch_bounds__(256)
void gather_kernel(const float* __restrict__ h) {
    int warp = (blockIdx.x * blockDim.x + threadIdx.x) >> 5;
    int lane = threadIdx.x & 31;
    if (warp >= NNODES) return;
    int beg = g_rowptr[warp];
    int end = g_rowptr[warp + 1];
    int half = lane >> 4;
    int fl   = lane & 15;

    const float4* hp = (const float4*)h;
    float ax = 0.f, ay = 0.f, az = 0.f, aw = 0.f;
#pragma unroll 4
    for (int j = beg + half; j < end; j += 2) {
        int s = g_adj[j];
        float4 v = __ldg(&hp[(size_t)s * 16 + fl]);
        ax += v.x; ay += v.y; az += v.z; aw += v.w;
    }
    ax += __shfl_xor_sync(0xffffffffu, ax, 16);
    ay += __shfl_xor_sync(0xffffffffu, ay, 16);
    az += __shfl_xor_sync(0xffffffffu, az, 16);
    aw += __shfl_xor_sync(0xffffffffu, aw, 16);

    if (half == 0) {
        float inv = 1.0f / fmaxf((float)(end - beg), 1.0f);
        float4 rr; rr.x = ax * inv; rr.y = ay * inv; rr.z = az * inv; rr.w = aw * inv;
        g_msg4[(size_t)warp * 16 + fl] = rr;
    }
}

// ---------------------------------------------------------------------------
// K6: final = relu(partial(out) + msg @ W2)   (R9-proven)
// ---------------------------------------------------------------------------
__global__ __launch_bounds__(256)
void k6_final(const float* __restrict__ W,
              float* __restrict__ out) {
    __shared__ float As[64 * 68];
    __shared__ float Ws[64 * 68];
    int tid = threadIdx.x;
    int gn = blockIdx.x * 64;

    ull acc[2][4];
#pragma unroll
    for (int j = 0; j < 2; j++)
#pragma unroll
        for (int oi = 0; oi < 4; oi++) acc[j][oi] = 0ULL;

    half_gemm((const float*)g_msg4, W, 64, gn, tid, As, Ws, acc);

    int n0 = (tid & 15) * 4;
    int o0 = (tid >> 4) * 4;
#pragma unroll
    for (int j = 0; j < 2; j++) {
        float x0[4], x1[4];
#pragma unroll
        for (int oi = 0; oi < 4; oi++) unpack2(acc[j][oi], x0[oi], x1[oi]);
        int n = gn + n0 + 2 * j;
        if (n < NNODES) {
            float4 p = *(const float4*)&out[(size_t)n * OUTF + o0];
            float4 rr;
            rr.x = fmaxf(p.x + x0[0], 0.0f);
            rr.y = fmaxf(p.y + x0[1], 0.0f);
            rr.z = fmaxf(p.z + x0[2], 0.0f);
            rr.w = fmaxf(p.w + x0[3], 0.0f);
            *(float4*)&out[(size_t)n * OUTF + o0] = rr;
        }
        if (n + 1 < NNODES) {
            float4 p = *(const float4*)&out[(size_t)(n + 1) * OUTF + o0];
            float4 rr;
            rr.x = fmaxf(p.x + x1[0], 0.0f);
            rr.y = fmaxf(p.y + x1[1], 0.0f);
            rr.z = fmaxf(p.z + x1[2], 0.0f);
            rr.w = fmaxf(p.w + x1[3], 0.0f);
            *(float4*)&out[(size_t)(n + 1) * OUTF + o0] = rr;
        }
    }
}

// ---------------------------------------------------------------------------
// inputs: h [N,64] f32, src [E] i32, dst [E] i32, W [64,128] f32, b [64] f32
// output: [N,64] f32
// ---------------------------------------------------------------------------
extern "C" void kernel_launch(void* const* d_in, const int* in_sizes, int n_in,
                              void* d_out, int out_size) {
    const float* h   = (const float*)d_in[0];
    const int*   src = (const int*)d_in[1];
    const int*   dst = (const int*)d_in[2];
    const float* W   = (const float*)d_in[3];
    const float* b   = (const float*)d_in[4];
    float*       out = (float*)d_out;

    int E = in_sizes[1];
    int eblocks = (E + 255) / 256;            // fill blocks (1 edge/thread)

    // interleave total: groups of 7 = 5 fill + 2 gemm; cover both ranges
    int qn = (eblocks + 4) / 5;
    int qg = (GEMM_BLOCKS + 1) / 2;
    int q = (qn > qg) ? qn : qg;
    int total_fp = q * 7;

    hist_kernel<<<eblocks, 256>>>(dst, E);
    scan_a_kernel<<<NB, 256>>>();
    scan_c_kernel<<<NB, 256>>>(E);
    fill_partial_kernel<<<total_fp, 256>>>(src, dst, E, eblocks, h, W, b, out);
    gather_kernel<<<(NNODES * 32 + 255) / 256, 256>>>(h);
    k6_final<<<GEMM_BLOCKS, 256>>>(W, out);
}